// round 3
// baseline (speedup 1.0000x reference)
#include <cuda_runtime.h>

#define DIM      1024
#define N_CLS    10
#define IMG      784
#define N_SAMP   16384
#define ROWS     4            // rows per warp
#define WARPS    8            // warps per block
#define TPB      (WARPS * 32)

// 40KB scratch for the normalized, zero-padded reference images
__device__ float d_ref[N_CLS * DIM];

// ---------------------------------------------------------------------------
// Kernel 1: ref[c][d] = canon[c][d] / ||canon[c]||  (d<784), else 0
// ---------------------------------------------------------------------------
__global__ void prep_ref_kernel(const float* __restrict__ canon) {
    __shared__ float red[256];
    const int c = blockIdx.x;
    const int t = threadIdx.x;

    float ss = 0.f;
    for (int i = t; i < IMG; i += 256) {
        float v = canon[c * IMG + i];
        ss += v * v;
    }
    red[t] = ss;
    __syncthreads();
    #pragma unroll
    for (int s = 128; s > 0; s >>= 1) {
        if (t < s) red[t] += red[t + s];
        __syncthreads();
    }
    const float inv = rsqrtf(red[0]);
    for (int d = t; d < DIM; d += 256) {
        d_ref[c * DIM + d] = (d < IMG) ? canon[c * IMG + d] * inv : 0.f;
    }
}

// ---------------------------------------------------------------------------
// Kernel 2: out[n][c] = (z_re[n]·ref[c])^2 + (z_im[n]·ref[c])^2
// Warp handles ROWS=4 consecutive rows; lane owns d = j*128 + lane*4 (float4).
// ref lives in shared (40KB), each ref LDS.128 reused across 4 rows.
// ---------------------------------------------------------------------------
__global__ void __launch_bounds__(TPB)
swap_test_kernel(const float* __restrict__ z_re,
                 const float* __restrict__ z_im,
                 float* __restrict__ out)
{
    __shared__ float4 ref_s[N_CLS * (DIM / 4)];   // 2560 float4 = 40KB

    const int t = threadIdx.x;
    {   // stage ref into shared
        const float4* refg = reinterpret_cast<const float4*>(d_ref);
        #pragma unroll
        for (int i = 0; i < (N_CLS * DIM / 4) / TPB; ++i)
            ref_s[i * TPB + t] = refg[i * TPB + t];
    }
    __syncthreads();

    const int warp = t >> 5;
    const int lane = t & 31;
    const int row0 = (blockIdx.x * WARPS + warp) * ROWS;

    float ar[ROWS][N_CLS];
    float ai[ROWS][N_CLS];
    #pragma unroll
    for (int r = 0; r < ROWS; ++r)
        #pragma unroll
        for (int c = 0; c < N_CLS; ++c) { ar[r][c] = 0.f; ai[r][c] = 0.f; }

    const float4* zr4 = reinterpret_cast<const float4*>(z_re) + (size_t)row0 * (DIM / 4);
    const float4* zi4 = reinterpret_cast<const float4*>(z_im) + (size_t)row0 * (DIM / 4);

    #pragma unroll 2
    for (int j = 0; j < DIM / 128; ++j) {       // 8 iterations, 128 d's each
        const int off = j * 32 + lane;          // float4 index within a row
        float4 zr[ROWS], zi[ROWS];
        #pragma unroll
        for (int r = 0; r < ROWS; ++r) {
            zr[r] = zr4[r * (DIM / 4) + off];
            zi[r] = zi4[r * (DIM / 4) + off];
        }
        #pragma unroll
        for (int c = 0; c < N_CLS; ++c) {
            const float4 f = ref_s[c * (DIM / 4) + off];
            #pragma unroll
            for (int r = 0; r < ROWS; ++r) {
                ar[r][c] += zr[r].x * f.x;
                ar[r][c] += zr[r].y * f.y;
                ar[r][c] += zr[r].z * f.z;
                ar[r][c] += zr[r].w * f.w;
                ai[r][c] += zi[r].x * f.x;
                ai[r][c] += zi[r].y * f.y;
                ai[r][c] += zi[r].z * f.z;
                ai[r][c] += zi[r].w * f.w;
            }
        }
    }

    // butterfly reduce all 80 accumulators across the warp
    #pragma unroll
    for (int s = 16; s > 0; s >>= 1) {
        #pragma unroll
        for (int r = 0; r < ROWS; ++r)
            #pragma unroll
            for (int c = 0; c < N_CLS; ++c) {
                ar[r][c] += __shfl_xor_sync(0xffffffffu, ar[r][c], s);
                ai[r][c] += __shfl_xor_sync(0xffffffffu, ai[r][c], s);
            }
    }

    // lane c writes class c for all 4 rows (every lane holds the full sums)
    if (lane < N_CLS) {
        #pragma unroll
        for (int c = 0; c < N_CLS; ++c) {
            if (lane == c) {
                #pragma unroll
                for (int r = 0; r < ROWS; ++r) {
                    const float re = ar[r][c];
                    const float im = ai[r][c];
                    out[(size_t)(row0 + r) * N_CLS + c] = re * re + im * im;
                }
            }
        }
    }
}

// ---------------------------------------------------------------------------
extern "C" void kernel_launch(void* const* d_in, const int* in_sizes, int n_in,
                              void* d_out, int out_size) {
    const float* z_re  = (const float*)d_in[0];
    const float* z_im  = (const float*)d_in[1];
    const float* canon = (const float*)d_in[2];
    float* out = (float*)d_out;

    prep_ref_kernel<<<N_CLS, 256>>>(canon);

    const int rows_per_block = WARPS * ROWS;               // 32
    swap_test_kernel<<<N_SAMP / rows_per_block, TPB>>>(z_re, z_im, out);
}

// round 4
// speedup vs baseline: 1.2535x; 1.2535x over previous
#include <cuda_runtime.h>

#define DIM      1024
#define N_CLS    10
#define IMG      784
#define N_SAMP   16384
#define ROWS     2            // rows per warp
#define WARPS    8            // warps per block
#define TPB      (WARPS * 32)

// 40KB scratch for the normalized, zero-padded reference images
__device__ float d_ref[N_CLS * DIM];

// packed f32x2 FMA: d = a*b + d  (two independent fp32 lanes in one instr)
__device__ __forceinline__ void ffma2(unsigned long long& d,
                                      unsigned long long a,
                                      unsigned long long b) {
    asm("fma.rn.f32x2 %0, %1, %2, %0;" : "+l"(d) : "l"(a), "l"(b));
}

__device__ __forceinline__ float pair_sum(unsigned long long v) {
    float lo = __uint_as_float((unsigned)(v & 0xffffffffu));
    float hi = __uint_as_float((unsigned)(v >> 32));
    return lo + hi;
}

// ---------------------------------------------------------------------------
// Kernel 1: ref[c][d] = canon[c][d] / ||canon[c]||  (d<784), else 0
// ---------------------------------------------------------------------------
__global__ void prep_ref_kernel(const float* __restrict__ canon) {
    __shared__ float red[256];
    const int c = blockIdx.x;
    const int t = threadIdx.x;

    float ss = 0.f;
    for (int i = t; i < IMG; i += 256) {
        float v = canon[c * IMG + i];
        ss += v * v;
    }
    red[t] = ss;
    __syncthreads();
    #pragma unroll
    for (int s = 128; s > 0; s >>= 1) {
        if (t < s) red[t] += red[t + s];
        __syncthreads();
    }
    const float inv = rsqrtf(red[0]);
    for (int d = t; d < DIM; d += 256) {
        d_ref[c * DIM + d] = (d < IMG) ? canon[c * IMG + d] * inv : 0.f;
    }
}

// ---------------------------------------------------------------------------
// Kernel 2: out[n][c] = (z_re[n]·ref[c])^2 + (z_im[n]·ref[c])^2
// Warp handles ROWS=2 rows; lane owns d = j*128 + lane*4 (one float4).
// All dot-product math in packed f32x2 FMAs: the two fp32 lanes of each
// 64-bit register hold (even d, odd d) partial sums. Operands come straight
// from the 64-bit halves of LDG.128 / LDS.128 results — no packing MOVs.
// ---------------------------------------------------------------------------
__global__ void __launch_bounds__(TPB, 2)
swap_test_kernel(const float* __restrict__ z_re,
                 const float* __restrict__ z_im,
                 float* __restrict__ out)
{
    __shared__ float4 ref_s[N_CLS * (DIM / 4)];   // 2560 float4 = 40KB

    const int t = threadIdx.x;
    {   // stage ref into shared
        const float4* refg = reinterpret_cast<const float4*>(d_ref);
        #pragma unroll
        for (int i = 0; i < (N_CLS * DIM / 4) / TPB; ++i)
            ref_s[i * TPB + t] = refg[i * TPB + t];
    }
    __syncthreads();

    const int warp = t >> 5;
    const int lane = t & 31;
    const int row0 = (blockIdx.x * WARPS + warp) * ROWS;

    // acc[r][c][0] = packed re partial sums (even d, odd d)
    // acc[r][c][1] = packed im partial sums
    unsigned long long acc[ROWS][N_CLS][2];
    #pragma unroll
    for (int r = 0; r < ROWS; ++r)
        #pragma unroll
        for (int c = 0; c < N_CLS; ++c) { acc[r][c][0] = 0ull; acc[r][c][1] = 0ull; }

    const ulonglong2* zr4 =
        reinterpret_cast<const ulonglong2*>(z_re) + (size_t)row0 * (DIM / 4);
    const ulonglong2* zi4 =
        reinterpret_cast<const ulonglong2*>(z_im) + (size_t)row0 * (DIM / 4);

    // double-buffered z loads: 8 LDG.128 in flight
    ulonglong2 czr[ROWS], czi[ROWS], nzr[ROWS], nzi[ROWS];
    #pragma unroll
    for (int r = 0; r < ROWS; ++r) {
        czr[r] = zr4[r * (DIM / 4) + lane];
        czi[r] = zi4[r * (DIM / 4) + lane];
    }

    #pragma unroll
    for (int j = 0; j < DIM / 128; ++j) {       // 8 iterations, 128 d's each
        if (j < DIM / 128 - 1) {
            const int offn = (j + 1) * 32 + lane;
            #pragma unroll
            for (int r = 0; r < ROWS; ++r) {
                nzr[r] = zr4[r * (DIM / 4) + offn];
                nzi[r] = zi4[r * (DIM / 4) + offn];
            }
        }
        const int off = j * 32 + lane;
        #pragma unroll
        for (int c = 0; c < N_CLS; ++c) {
            const ulonglong2 f2 =
                *reinterpret_cast<const ulonglong2*>(&ref_s[c * (DIM / 4) + off]);
            #pragma unroll
            for (int r = 0; r < ROWS; ++r) {
                ffma2(acc[r][c][0], czr[r].x, f2.x);
                ffma2(acc[r][c][0], czr[r].y, f2.y);
                ffma2(acc[r][c][1], czi[r].x, f2.x);
                ffma2(acc[r][c][1], czi[r].y, f2.y);
            }
        }
        #pragma unroll
        for (int r = 0; r < ROWS; ++r) { czr[r] = nzr[r]; czi[r] = nzi[r]; }
    }

    // collapse even/odd packed halves, then butterfly-reduce across the warp
    float sr[ROWS][N_CLS], si[ROWS][N_CLS];
    #pragma unroll
    for (int r = 0; r < ROWS; ++r)
        #pragma unroll
        for (int c = 0; c < N_CLS; ++c) {
            sr[r][c] = pair_sum(acc[r][c][0]);
            si[r][c] = pair_sum(acc[r][c][1]);
        }

    #pragma unroll
    for (int s = 16; s > 0; s >>= 1) {
        #pragma unroll
        for (int r = 0; r < ROWS; ++r)
            #pragma unroll
            for (int c = 0; c < N_CLS; ++c) {
                sr[r][c] += __shfl_xor_sync(0xffffffffu, sr[r][c], s);
                si[r][c] += __shfl_xor_sync(0xffffffffu, si[r][c], s);
            }
    }

    // lane c writes class c for both rows (every lane holds the full sums)
    #pragma unroll
    for (int c = 0; c < N_CLS; ++c) {
        if (lane == c) {
            #pragma unroll
            for (int r = 0; r < ROWS; ++r) {
                const float re = sr[r][c];
                const float im = si[r][c];
                out[(size_t)(row0 + r) * N_CLS + c] = re * re + im * im;
            }
        }
    }
}

// ---------------------------------------------------------------------------
extern "C" void kernel_launch(void* const* d_in, const int* in_sizes, int n_in,
                              void* d_out, int out_size) {
    const float* z_re  = (const float*)d_in[0];
    const float* z_im  = (const float*)d_in[1];
    const float* canon = (const float*)d_in[2];
    float* out = (float*)d_out;

    prep_ref_kernel<<<N_CLS, 256>>>(canon);

    const int rows_per_block = WARPS * ROWS;               // 16
    swap_test_kernel<<<N_SAMP / rows_per_block, TPB>>>(z_re, z_im, out);
}

// round 5
// speedup vs baseline: 1.4002x; 1.1170x over previous
#include <cuda_runtime.h>

#define DIM    1024
#define NF4    (DIM / 4)          // 256 float4 per row
#define N_CLS  10
#define IMG    784                // = 196 float4, exactly f4-aligned
#define IMGF4  (IMG / 4)
#define N_SAMP 16384
#define ROWS   2                  // rows per warp
#define WARPS  8
#define TPB    256
#define RB     (WARPS * ROWS)     // 16 rows per block
#define JIT    8                  // DIM / 128 j-iterations
#define DEPTH  3                  // cp.async pipeline stages
#define REF_F4 (N_CLS * NF4)      // 2560 float4 = 40KB
#define STG_F4 (2 * RB * 32)      // 1024 float4 = 16KB per stage
#define SMEM_BYTES ((REF_F4 + DEPTH * STG_F4) * 16 + 96 * 4)

// packed f32x2 FMA: d = a*b + d  (two independent fp32 lanes per instr)
__device__ __forceinline__ void ffma2(unsigned long long& d,
                                      unsigned long long a,
                                      unsigned long long b) {
    asm("fma.rn.f32x2 %0, %1, %2, %0;" : "+l"(d) : "l"(a), "l"(b));
}

__device__ __forceinline__ float pair_sum(unsigned long long v) {
    float lo = __uint_as_float((unsigned)(v & 0xffffffffu));
    float hi = __uint_as_float((unsigned)(v >> 32));
    return lo + hi;
}

__device__ __forceinline__ void cp_async16(void* smem_dst, const void* gsrc) {
    unsigned saddr = (unsigned)__cvta_generic_to_shared(smem_dst);
    asm volatile("cp.async.cg.shared.global [%0], [%1], 16;"
                 :: "r"(saddr), "l"(gsrc));
}
__device__ __forceinline__ void cp_commit() {
    asm volatile("cp.async.commit_group;");
}
template <int N>
__device__ __forceinline__ void cp_wait() {
    asm volatile("cp.async.wait_group %0;" :: "n"(N));
}

// ---------------------------------------------------------------------------
// out[n][c] = (z_re[n]·ref[c])^2 + (z_im[n]·ref[c])^2
// z streamed via depth-3 cp.async smem pipeline; ref normalized in-kernel
// (redundantly per block, hidden under the async prologue) and held in smem.
// All dot math in packed f32x2 FMAs.
// ---------------------------------------------------------------------------
__global__ void __launch_bounds__(TPB, 2)
swap_test_kernel(const float* __restrict__ z_re,
                 const float* __restrict__ z_im,
                 const float* __restrict__ canon,
                 float* __restrict__ out)
{
    extern __shared__ float4 smem[];
    float4* ref_s = smem;                        // [N_CLS][NF4]
    float4* zst   = smem + REF_F4;               // [DEPTH][2][RB][32]
    float*  scr   = (float*)(zst + DEPTH * STG_F4);  // 80 partials + 10 inv

    const int t    = threadIdx.x;
    const int warp = t >> 5;
    const int lane = t & 31;
    const int row0 = blockIdx.x * RB;
    const float4* zr4 = (const float4*)z_re;
    const float4* zi4 = (const float4*)z_im;

    // ---- prologue: kick off DRAM traffic for stages 0..DEPTH-1 ------------
    #pragma unroll
    for (int s = 0; s < DEPTH; ++s) {
        #pragma unroll
        for (int k = 0; k < 4; ++k) {
            const int idx   = k * TPB + t;        // 0..1023
            const int plane = idx >> 9;           // warp-uniform per k
            const int rr    = (idx >> 5) & 15;
            const int col   = idx & 31;
            const float4* src = (plane ? zi4 : zr4)
                                + (size_t)(row0 + rr) * NF4 + s * 32 + col;
            cp_async16(&zst[s * STG_F4 + plane * (RB * 32) + rr * 32 + col], src);
        }
        cp_commit();
    }

    // ---- fused ref prep (overlapped with prologue DRAM latency) -----------
    {
        float ss[N_CLS];
        #pragma unroll
        for (int c = 0; c < N_CLS; ++c) ss[c] = 0.f;
        for (int i = t; i < IMG; i += TPB) {
            #pragma unroll
            for (int c = 0; c < N_CLS; ++c) {
                const float v = canon[c * IMG + i];
                ss[c] += v * v;
            }
        }
        #pragma unroll
        for (int c = 0; c < N_CLS; ++c)
            #pragma unroll
            for (int sh = 16; sh > 0; sh >>= 1)
                ss[c] += __shfl_xor_sync(0xffffffffu, ss[c], sh);
        if (lane == 0) {
            #pragma unroll
            for (int c = 0; c < N_CLS; ++c) scr[c * WARPS + warp] = ss[c];
        }
        __syncthreads();
        if (t < N_CLS) {
            float s = 0.f;
            #pragma unroll
            for (int w = 0; w < WARPS; ++w) s += scr[t * WARPS + w];
            scr[80 + t] = rsqrtf(s);
        }
        __syncthreads();
        const float4* cg4 = (const float4*)canon;   // 3136B/class: f4-aligned
        #pragma unroll
        for (int i = 0; i < REF_F4 / TPB; ++i) {
            const int idx = i * TPB + t;
            const int c   = idx / NF4;
            const int d4  = idx % NF4;
            const float inv = scr[80 + c];
            float4 v = make_float4(0.f, 0.f, 0.f, 0.f);
            if (d4 < IMGF4) {
                const float4 u = cg4[c * IMGF4 + d4];
                v = make_float4(u.x * inv, u.y * inv, u.z * inv, u.w * inv);
            }
            ref_s[idx] = v;
        }
        __syncthreads();
    }

    // ---- main pipelined loop ---------------------------------------------
    unsigned long long accR[ROWS][N_CLS], accI[ROWS][N_CLS];
    #pragma unroll
    for (int r = 0; r < ROWS; ++r)
        #pragma unroll
        for (int c = 0; c < N_CLS; ++c) { accR[r][c] = 0ull; accI[r][c] = 0ull; }

    #pragma unroll
    for (int j = 0; j < JIT; ++j) {
        cp_wait<DEPTH - 1>();      // with always-commit, guarantees stage j done
        __syncthreads();

        const int b = j % DEPTH;
        ulonglong2 zr_[ROWS], zi_[ROWS];
        #pragma unroll
        for (int r = 0; r < ROWS; ++r) {
            const int rr = warp * ROWS + r;
            zr_[r] = *(const ulonglong2*)&zst[b * STG_F4 + rr * 32 + lane];
            zi_[r] = *(const ulonglong2*)&zst[b * STG_F4 + RB * 32 + rr * 32 + lane];
        }
        #pragma unroll
        for (int c = 0; c < N_CLS; ++c) {
            const ulonglong2 f2 =
                *(const ulonglong2*)&ref_s[c * NF4 + j * 32 + lane];
            #pragma unroll
            for (int r = 0; r < ROWS; ++r) {
                ffma2(accR[r][c], zr_[r].x, f2.x);
                ffma2(accR[r][c], zr_[r].y, f2.y);
                ffma2(accI[r][c], zi_[r].x, f2.x);
                ffma2(accI[r][c], zi_[r].y, f2.y);
            }
        }
        __syncthreads();           // all warps done reading buf b

        if (j + DEPTH < JIT) {     // refill buf b with stage j+DEPTH
            #pragma unroll
            for (int k = 0; k < 4; ++k) {
                const int idx   = k * TPB + t;
                const int plane = idx >> 9;
                const int rr    = (idx >> 5) & 15;
                const int col   = idx & 31;
                const float4* src = (plane ? zi4 : zr4)
                    + (size_t)(row0 + rr) * NF4 + (j + DEPTH) * 32 + col;
                cp_async16(&zst[b * STG_F4 + plane * (RB * 32) + rr * 32 + col], src);
            }
        }
        cp_commit();               // always commit (possibly empty group)
    }

    // ---- reduce & write ---------------------------------------------------
    float sr[ROWS][N_CLS], si[ROWS][N_CLS];
    #pragma unroll
    for (int r = 0; r < ROWS; ++r)
        #pragma unroll
        for (int c = 0; c < N_CLS; ++c) {
            sr[r][c] = pair_sum(accR[r][c]);
            si[r][c] = pair_sum(accI[r][c]);
        }

    #pragma unroll
    for (int s = 16; s > 0; s >>= 1)
        #pragma unroll
        for (int r = 0; r < ROWS; ++r)
            #pragma unroll
            for (int c = 0; c < N_CLS; ++c) {
                sr[r][c] += __shfl_xor_sync(0xffffffffu, sr[r][c], s);
                si[r][c] += __shfl_xor_sync(0xffffffffu, si[r][c], s);
            }

    const int rowbase = row0 + warp * ROWS;
    #pragma unroll
    for (int c = 0; c < N_CLS; ++c) {
        if (lane == c) {
            #pragma unroll
            for (int r = 0; r < ROWS; ++r) {
                const float re = sr[r][c];
                const float im = si[r][c];
                out[(size_t)(rowbase + r) * N_CLS + c] = re * re + im * im;
            }
        }
    }
}

// ---------------------------------------------------------------------------
extern "C" void kernel_launch(void* const* d_in, const int* in_sizes, int n_in,
                              void* d_out, int out_size) {
    const float* z_re  = (const float*)d_in[0];
    const float* z_im  = (const float*)d_in[1];
    const float* canon = (const float*)d_in[2];
    float* out = (float*)d_out;

    static bool attr_set = false;
    if (!attr_set) {
        cudaFuncSetAttribute(swap_test_kernel,
                             cudaFuncAttributeMaxDynamicSharedMemorySize,
                             SMEM_BYTES);
        attr_set = true;
    }

    swap_test_kernel<<<N_SAMP / RB, TPB, SMEM_BYTES>>>(z_re, z_im, canon, out);
}

// round 6
// speedup vs baseline: 1.7128x; 1.2233x over previous
#include <cuda_runtime.h>

#define DIM     1024
#define NF4     256               // float4 per row
#define N_CLS   10
#define IMG     784
#define IMGF4   196
#define N_SAMP  16384
#define ROWS    2                 // rows per warp
#define WARPS   8
#define TPB     256
#define RB      16                // rows per tile (= WARPS*ROWS)
#define NTILES  (N_SAMP / RB)     // 1024
#define GRID    304               // 2 blocks per SM on 152 SMs
#define BASE_T  (NTILES / GRID)   // 3
#define REM_T   (NTILES - BASE_T * GRID)  // 112 blocks get one extra tile
#define JIT     8                 // chunks per tile (128 d each)
#define DEPTH   4                 // per-warp cp.async stages
#define REF_F4  (N_CLS * NF4)     // 2560 float4 = 40KB
#define WSTG_F4 128               // per warp per slot: {re,im}x{r0,r1}x32 f4 = 2KB
#define STG_F4  (WARPS * DEPTH * WSTG_F4)   // 4096 f4 = 64KB
#define SMEM_BYTES ((REF_F4 + STG_F4) * 16 + 96 * 4)

// ---- packed fp32x2 helpers -------------------------------------------------
__device__ __forceinline__ void ffma2(unsigned long long& d,
                                      unsigned long long a,
                                      unsigned long long b) {
    asm("fma.rn.f32x2 %0, %1, %2, %0;" : "+l"(d) : "l"(a), "l"(b));
}
__device__ __forceinline__ unsigned long long addf2(unsigned long long a,
                                                    unsigned long long b) {
    asm("add.rn.f32x2 %0, %1, %2;" : "+l"(a) : "l"(a), "l"(b));
    return a;
}
__device__ __forceinline__ float pair_sum(unsigned long long v) {
    return __uint_as_float((unsigned)(v & 0xffffffffu)) +
           __uint_as_float((unsigned)(v >> 32));
}
__device__ __forceinline__ unsigned long long packf2(float lo, float hi) {
    return ((unsigned long long)__float_as_uint(hi) << 32) | __float_as_uint(lo);
}

// ---- cp.async helpers ------------------------------------------------------
__device__ __forceinline__ void cp_async16(void* smem_dst, const void* gsrc) {
    unsigned saddr = (unsigned)__cvta_generic_to_shared(smem_dst);
    asm volatile("cp.async.cg.shared.global [%0], [%1], 16;"
                 :: "r"(saddr), "l"(gsrc));
}
__device__ __forceinline__ void cp_commit() {
    asm volatile("cp.async.commit_group;");
}
template <int N>
__device__ __forceinline__ void cp_wait() {
    asm volatile("cp.async.wait_group %0;" :: "n"(N));
}

// ---------------------------------------------------------------------------
// out[n][c] = (z_re[n]·ref[c])^2 + (z_im[n]·ref[c])^2
// Persistent blocks (2/SM). Each WARP runs its own DEPTH-4 cp.async pipeline
// over its 2 rows per tile — no __syncthreads in the main loop at all.
// ref normalized once per block into smem; all dot math in packed f32x2 FMA.
// ---------------------------------------------------------------------------
__global__ void __launch_bounds__(TPB, 2)
swap_test_kernel(const float* __restrict__ z_re,
                 const float* __restrict__ z_im,
                 const float* __restrict__ canon,
                 float* __restrict__ out)
{
    extern __shared__ float4 smem[];
    float4* ref_s = smem;                          // [N_CLS][NF4]
    float4* zst   = smem + REF_F4;                 // [WARPS][DEPTH][128]
    float*  scr   = (float*)(zst + STG_F4);        // 80 partials + 10 inv

    const int t    = threadIdx.x;
    const int warp = t >> 5;
    const int lane = t & 31;
    const int b    = blockIdx.x;

    const int tile0  = BASE_T * b + min(b, REM_T);
    const int ntiles = BASE_T + (b < REM_T ? 1 : 0);
    const int nchunks = ntiles * JIT;

    const float4* zr4 = (const float4*)z_re;
    const float4* zi4 = (const float4*)z_im;
    float4* mystg = zst + warp * (DEPTH * WSTG_F4);

    // ---- prologue: fill this warp's DEPTH slots (chunks 0..DEPTH-1) -------
    {
        const size_t row = (size_t)tile0 * RB + warp * ROWS;
        const float4* br = zr4 + row * NF4 + lane;
        const float4* bi = zi4 + row * NF4 + lane;
        #pragma unroll
        for (int s = 0; s < DEPTH; ++s) {
            float4* dst = mystg + s * WSTG_F4;
            cp_async16(&dst[lane],      br + s * 32);
            cp_async16(&dst[32 + lane], br + NF4 + s * 32);
            cp_async16(&dst[64 + lane], bi + s * 32);
            cp_async16(&dst[96 + lane], bi + NF4 + s * 32);
            cp_commit();
        }
    }

    // ---- ref prep once per block (hidden under prologue DRAM latency) -----
    {
        float ss[N_CLS];
        #pragma unroll
        for (int c = 0; c < N_CLS; ++c) ss[c] = 0.f;
        for (int i = t; i < IMG; i += TPB) {
            #pragma unroll
            for (int c = 0; c < N_CLS; ++c) {
                const float v = canon[c * IMG + i];
                ss[c] += v * v;
            }
        }
        #pragma unroll
        for (int c = 0; c < N_CLS; ++c)
            #pragma unroll
            for (int sh = 16; sh > 0; sh >>= 1)
                ss[c] += __shfl_xor_sync(0xffffffffu, ss[c], sh);
        if (lane == 0) {
            #pragma unroll
            for (int c = 0; c < N_CLS; ++c) scr[c * WARPS + warp] = ss[c];
        }
        __syncthreads();
        if (t < N_CLS) {
            float s = 0.f;
            #pragma unroll
            for (int w = 0; w < WARPS; ++w) s += scr[t * WARPS + w];
            scr[80 + t] = rsqrtf(s);
        }
        __syncthreads();
        const float4* cg4 = (const float4*)canon;
        #pragma unroll
        for (int i = 0; i < REF_F4 / TPB; ++i) {
            const int idx = i * TPB + t;
            const int c   = idx / NF4;
            const int d4  = idx % NF4;
            const float inv = scr[80 + c];
            float4 v = make_float4(0.f, 0.f, 0.f, 0.f);
            if (d4 < IMGF4) {
                const float4 u = cg4[c * IMGF4 + d4];
                v = make_float4(u.x * inv, u.y * inv, u.z * inv, u.w * inv);
            }
            ref_s[idx] = v;
        }
        __syncthreads();
    }

    // ---- main loop: per-warp pipeline, no block barriers ------------------
    int pf_tl = 0, pf_j = DEPTH;      // next chunk to prefetch = chunk DEPTH
    int q = 0;

    for (int tl = 0; tl < ntiles; ++tl) {
        unsigned long long accR[ROWS][N_CLS], accI[ROWS][N_CLS];
        #pragma unroll
        for (int r = 0; r < ROWS; ++r)
            #pragma unroll
            for (int c = 0; c < N_CLS; ++c) { accR[r][c] = 0ull; accI[r][c] = 0ull; }

        #pragma unroll
        for (int j = 0; j < JIT; ++j, ++q) {
            const int slot = q & (DEPTH - 1);
            cp_wait<DEPTH - 1>();                  // chunk q's data is in smem

            const float4* s = mystg + slot * WSTG_F4;
            const ulonglong2 zr0 = *(const ulonglong2*)&s[lane];
            const ulonglong2 zr1 = *(const ulonglong2*)&s[32 + lane];
            const ulonglong2 zi0 = *(const ulonglong2*)&s[64 + lane];
            const ulonglong2 zi1 = *(const ulonglong2*)&s[96 + lane];

            // refill this slot with chunk q+DEPTH (same slot index).
            // WAR on smem is physically safe: global return >> LDS latency.
            if (q + DEPTH < nchunks) {
                const size_t row = (size_t)(tile0 + pf_tl) * RB + warp * ROWS;
                const float4* br = zr4 + row * NF4 + pf_j * 32 + lane;
                const float4* bi = zi4 + row * NF4 + pf_j * 32 + lane;
                float4* dst = mystg + slot * WSTG_F4;
                cp_async16(&dst[lane],      br);
                cp_async16(&dst[32 + lane], br + NF4);
                cp_async16(&dst[64 + lane], bi);
                cp_async16(&dst[96 + lane], bi + NF4);
            }
            cp_commit();                           // always commit (may be empty)
            if (++pf_j == JIT) { pf_j = 0; ++pf_tl; }

            const float4* rbase = ref_s + j * 32 + lane;
            #pragma unroll
            for (int c = 0; c < N_CLS; ++c) {
                const ulonglong2 f2 = *(const ulonglong2*)&rbase[c * NF4];
                ffma2(accR[0][c], zr0.x, f2.x);
                ffma2(accR[0][c], zr0.y, f2.y);
                ffma2(accR[1][c], zr1.x, f2.x);
                ffma2(accR[1][c], zr1.y, f2.y);
                ffma2(accI[0][c], zi0.x, f2.x);
                ffma2(accI[0][c], zi0.y, f2.y);
                ffma2(accI[1][c], zi1.x, f2.x);
                ffma2(accI[1][c], zi1.y, f2.y);
            }
        }

        // ---- tile epilogue: packed (re,im) butterfly, then write ----------
        unsigned long long pk[ROWS][N_CLS];
        #pragma unroll
        for (int r = 0; r < ROWS; ++r)
            #pragma unroll
            for (int c = 0; c < N_CLS; ++c)
                pk[r][c] = packf2(pair_sum(accR[r][c]), pair_sum(accI[r][c]));

        #pragma unroll
        for (int sh = 16; sh > 0; sh >>= 1)
            #pragma unroll
            for (int r = 0; r < ROWS; ++r)
                #pragma unroll
                for (int c = 0; c < N_CLS; ++c)
                    pk[r][c] = addf2(pk[r][c],
                                     __shfl_xor_sync(0xffffffffu, pk[r][c], sh));

        const size_t rowbase = (size_t)(tile0 + tl) * RB + warp * ROWS;
        #pragma unroll
        for (int c = 0; c < N_CLS; ++c) {
            if (lane == c) {
                #pragma unroll
                for (int r = 0; r < ROWS; ++r) {
                    const float re = __uint_as_float((unsigned)(pk[r][c] & 0xffffffffu));
                    const float im = __uint_as_float((unsigned)(pk[r][c] >> 32));
                    out[(rowbase + r) * N_CLS + c] = re * re + im * im;
                }
            }
        }
    }
}

// ---------------------------------------------------------------------------
extern "C" void kernel_launch(void* const* d_in, const int* in_sizes, int n_in,
                              void* d_out, int out_size) {
    const float* z_re  = (const float*)d_in[0];
    const float* z_im  = (const float*)d_in[1];
    const float* canon = (const float*)d_in[2];
    float* out = (float*)d_out;

    static bool attr_set = false;
    if (!attr_set) {
        cudaFuncSetAttribute(swap_test_kernel,
                             cudaFuncAttributeMaxDynamicSharedMemorySize,
                             SMEM_BYTES);
        attr_set = true;
    }

    swap_test_kernel<<<GRID, TPB, SMEM_BYTES>>>(z_re, z_im, canon, out);
}